// round 9
// baseline (speedup 1.0000x reference)
#include <cuda_runtime.h>
#include <cuda_bf16.h>
#include <cstdint>

// Problem constants
#define NB      1024
#define SEQT    512
#define UNITS_  256
#define NCHARS  128
#define ZC      1024      // 4*UNITS

// Tiling: 128 blocks = 16 batch-tiles x 8 hidden-tiles
#define BM      64        // batch rows per block (GEMM M)
#define HN      32        // hidden units per block
#define BC      128       // z cols per block (GEMM N), interleaved (unit,gate)
#define NBT     16
#define NHT     8
#define NBLK    128
#define NTHR    256

#define KDIM    256       // GEMM K
#define KPB     528       // padded row bytes (264 bf16)

// Shared memory layout (bytes)
#define OFF_WHI   0                         // Whi: [128 n][264 k] bf16 = 67584
#define OFF_WLO   67584                     // Wlo: 67584
#define OFF_AHI   135168                    // Ahi: [64 r][264 k] bf16 = 33792
#define OFF_ALO   168960                    // Alo: 33792
#define SMEM_TOTAL 202752

// Device-global scratch (zero-init at load)
__device__ unsigned int g_hx[2][NB * UNITS_];   // packed (bf16 hi | bf16 lo<<16)
__device__ unsigned int g_count, g_gen;

__device__ __forceinline__ float fast_sigmoid(float x) {
    return __fdividef(1.0f, 1.0f + __expf(-x));
}
__device__ __forceinline__ float fast_tanh(float x) {
    float e = __expf(2.0f * x);
    return 1.0f - __fdividef(2.0f, e + 1.0f);
}

// m16n8k16 row.col bf16 -> fp32 accumulate (baseline PTX, legal on sm_103)
__device__ __forceinline__ void mma16816(float& c0, float& c1, float& c2, float& c3,
                                         uint32_t a0, uint32_t a1, uint32_t a2, uint32_t a3,
                                         uint32_t b0, uint32_t b1) {
    asm volatile(
        "mma.sync.aligned.m16n8k16.row.col.f32.bf16.bf16.f32 "
        "{%0,%1,%2,%3}, {%4,%5,%6,%7}, {%8,%9}, {%0,%1,%2,%3};"
        : "+f"(c0), "+f"(c1), "+f"(c2), "+f"(c3)
        : "r"(a0), "r"(a1), "r"(a2), "r"(a3), "r"(b0), "r"(b1));
}

// Sense-reversing grid barrier; all NBLK CTAs co-resident (1 CTA/SM, single wave)
__device__ __forceinline__ void grid_barrier() {
    __syncthreads();
    if (threadIdx.x == 0) {
        __threadfence();
        unsigned int gen = *(volatile unsigned int*)&g_gen;
        unsigned int c = atomicAdd(&g_count, 1u);
        if (c == NBLK - 1u) {
            atomicExch(&g_count, 0u);
            __threadfence();
            atomicAdd(&g_gen, 1u);
        } else {
            while (*(volatile unsigned int*)&g_gen == gen) { __nanosleep(32); }
        }
        __threadfence();
    }
    __syncthreads();
}

extern "C" __global__ void __launch_bounds__(NTHR, 1)
lstm_hmma_kernel(const int*   __restrict__ inputs,   // [NB, SEQT]
                 const float* __restrict__ Wx,       // [NCHARS, ZC]
                 const float* __restrict__ Wh,       // [UNITS, ZC]
                 const float* __restrict__ bias,     // [ZC]
                 const float* __restrict__ Wd,       // [UNITS, NCHARS]
                 const float* __restrict__ bd,       // [NCHARS]
                 float*       __restrict__ out)      // [NB, NCHARS]
{
    extern __shared__ char smem[];

    const int tid  = threadIdx.x;
    const int wid  = tid >> 5;
    const int lane = tid & 31;
    const int bt   = blockIdx.x & (NBT - 1);
    const int ht   = blockIdx.x >> 4;
    const int b0   = bt * BM;

    // ---- One-time: Wh slice -> bf16 hi/lo, INTERLEAVED cols: n = 4*unit + gate ----
    // local col n -> global col: gate(n&3)*256 + ht*32 + unit(n>>2)
    for (int idx = tid; idx < BC * KDIM; idx += NTHR) {
        int n = idx >> 8;          // 0..127
        int k = idx & 255;         // 0..255
        int gcol = ((n & 3) << 8) + ht * HN + (n >> 2);
        float w = Wh[k * ZC + gcol];
        __nv_bfloat16 hi = __float2bfloat16(w);
        __nv_bfloat16 lo = __float2bfloat16(w - __bfloat162float(hi));
        *(__nv_bfloat16*)(smem + OFF_WHI + n * KPB + k * 2) = hi;
        *(__nv_bfloat16*)(smem + OFF_WLO + n * KPB + k * 2) = lo;
    }

    // MMA warp mapping: warp tile m32 x n32; Wm=2 (wm=wid&1), Wn=4 (wn=wid>>1)
    const int g    = lane >> 2;    // 0..7
    const int tg   = lane & 3;     // 0..3
    const int todd = tg & 1;       // 0: handles row g, 1: handles row g+8
    const int wm   = wid & 1;
    const int wn   = wid >> 1;

    // Units owned by this thread: uloc[j] = 8*wn + 2*j + (tg>>1)
    int uloc[4];
#pragma unroll
    for (int j = 0; j < 4; j++) uloc[j] = 8 * wn + 2 * j + (tg >> 1);

    // Bias -> registers (interleaved cols never touch smem at steady state)
    float breg[4][4];
#pragma unroll
    for (int j = 0; j < 4; j++) {
#pragma unroll
        for (int gt = 0; gt < 4; gt++)
            breg[j][gt] = __ldg(&bias[gt * 256 + ht * HN + uloc[j]]);
    }

    // Rows owned by this thread (one per m-subtile)
    int rowb[2];
#pragma unroll
    for (int ms = 0; ms < 2; ms++) rowb[ms] = 32 * wm + 16 * ms + g + (todd ? 8 : 0);

    float creg[2][4];
#pragma unroll
    for (int ms = 0; ms < 2; ms++)
#pragma unroll
        for (int j = 0; j < 4; j++) creg[ms][j] = 0.0f;

    // Fragment smem offsets
    const int aoffh = OFF_AHI + (32 * wm + g) * KPB + 4 * tg;   // msub adds 16*KPB
    const int aoffl = OFF_ALO + (32 * wm + g) * KPB + 4 * tg;
    const int boffh = OFF_WHI + (32 * wn + g) * KPB + 4 * tg;   // j adds 8*KPB
    const int boffl = OFF_WLO + (32 * wn + g) * KPB + 4 * tg;

    __syncthreads();

    for (int t = 0; t < SEQT; t++) {
        const int cur = t & 1;
        const int nxt = cur ^ 1;

        // ---- Chars for my 2 rows ----
        int ch[2];
#pragma unroll
        for (int ms = 0; ms < 2; ms++)
            ch[ms] = __ldg(&inputs[(b0 + rowb[ms]) * SEQT + t]);

        if (t > 0) {
            // ---- Stage A: split packed h into bf16 hi/lo tiles [64][264] ----
            for (int gidx = tid; gidx < BM * 64; gidx += NTHR) {
                int r  = gidx >> 6;
                int k0 = (gidx & 63) << 2;
                uint4 p = *(const uint4*)&g_hx[cur][(b0 + r) * UNITS_ + k0];
                uint32_t hi01 = __byte_perm(p.x, p.y, 0x5410);
                uint32_t hi23 = __byte_perm(p.z, p.w, 0x5410);
                uint32_t lo01 = __byte_perm(p.x, p.y, 0x7632);
                uint32_t lo23 = __byte_perm(p.z, p.w, 0x7632);
                uint32_t byte = (uint32_t)(r * KPB + k0 * 2);
                *(uint2*)(smem + OFF_AHI + byte) = make_uint2(hi01, hi23);
                *(uint2*)(smem + OFF_ALO + byte) = make_uint2(lo01, lo23);
            }
        }

        // ---- Wx gather for my (row, unit) cells: overlaps staging/MMA latency ----
        float xv[2][4][4];
#pragma unroll
        for (int ms = 0; ms < 2; ms++) {
            const float* wxr = Wx + ch[ms] * ZC + ht * HN;
#pragma unroll
            for (int j = 0; j < 4; j++) {
                xv[ms][j][0] = __ldg(wxr + uloc[j]);
                xv[ms][j][1] = __ldg(wxr + 256 + uloc[j]);
                xv[ms][j][2] = __ldg(wxr + 512 + uloc[j]);
                xv[ms][j][3] = __ldg(wxr + 768 + uloc[j]);
            }
        }

        float acc[2][4][4];
#pragma unroll
        for (int ms = 0; ms < 2; ms++)
#pragma unroll
            for (int j = 0; j < 4; j++) {
                acc[ms][j][0] = 0.f; acc[ms][j][1] = 0.f;
                acc[ms][j][2] = 0.f; acc[ms][j][3] = 0.f;
            }

        if (t > 0) {
            __syncthreads();   // staging complete before fragment reads

            // ---- MMA: C[64][128] = Ahi*Whi + Alo*Whi + Ahi*Wlo ----
#pragma unroll 2
            for (int kc = 0; kc < 16; kc++) {
                const int kb = kc * 32;   // 16 bf16 = 32 bytes
                uint32_t ah[2][4], al[2][4];
#pragma unroll
                for (int ms = 0; ms < 2; ms++) {
                    int ab = aoffh + ms * 16 * KPB + kb;
                    ah[ms][0] = *(const uint32_t*)(smem + ab);
                    ah[ms][1] = *(const uint32_t*)(smem + ab + 8 * KPB);
                    ah[ms][2] = *(const uint32_t*)(smem + ab + 16);
                    ah[ms][3] = *(const uint32_t*)(smem + ab + 8 * KPB + 16);
                    int abl = aoffl + ms * 16 * KPB + kb;
                    al[ms][0] = *(const uint32_t*)(smem + abl);
                    al[ms][1] = *(const uint32_t*)(smem + abl + 8 * KPB);
                    al[ms][2] = *(const uint32_t*)(smem + abl + 16);
                    al[ms][3] = *(const uint32_t*)(smem + abl + 8 * KPB + 16);
                }
#pragma unroll
                for (int j = 0; j < 4; j++) {
                    int bb = boffh + j * 8 * KPB + kb;
                    uint32_t bh0 = *(const uint32_t*)(smem + bb);
                    uint32_t bh1 = *(const uint32_t*)(smem + bb + 16);
                    int bbl = boffl + j * 8 * KPB + kb;
                    uint32_t bl0 = *(const uint32_t*)(smem + bbl);
                    uint32_t bl1 = *(const uint32_t*)(smem + bbl + 16);
#pragma unroll
                    for (int ms = 0; ms < 2; ms++) {
                        mma16816(acc[ms][j][0], acc[ms][j][1], acc[ms][j][2], acc[ms][j][3],
                                 ah[ms][0], ah[ms][1], ah[ms][2], ah[ms][3], bh0, bh1);
                        mma16816(acc[ms][j][0], acc[ms][j][1], acc[ms][j][2], acc[ms][j][3],
                                 al[ms][0], al[ms][1], al[ms][2], al[ms][3], bh0, bh1);
                        mma16816(acc[ms][j][0], acc[ms][j][1], acc[ms][j][2], acc[ms][j][3],
                                 ah[ms][0], ah[ms][1], ah[ms][2], ah[ms][3], bl0, bl1);
                    }
                }
            }
        }

        // ---- Gate phase straight from accumulators (one shfl pair exchange) ----
        // Even tg owns row g (c0,c1 = gates of its col pair), odd tg owns row g+8.
#pragma unroll
        for (int ms = 0; ms < 2; ms++) {
#pragma unroll
            for (int j = 0; j < 4; j++) {
                float c0 = acc[ms][j][0], c1 = acc[ms][j][1];
                float c2 = acc[ms][j][2], c3 = acc[ms][j][3];
                float x0 = __shfl_xor_sync(0xFFFFFFFFu, c0, 1);
                float x1 = __shfl_xor_sync(0xFFFFFFFFu, c1, 1);
                float x2 = __shfl_xor_sync(0xFFFFFFFFu, c2, 1);
                float x3 = __shfl_xor_sync(0xFFFFFFFFu, c3, 1);
                float zi, zf, zg, zo;
                if (todd) { zi = x2; zf = x3; zg = c2; zo = c3; }
                else      { zi = c0; zf = c1; zg = x0; zo = x1; }
                zi += xv[ms][j][0] + breg[j][0];
                zf += xv[ms][j][1] + breg[j][1];
                zg += xv[ms][j][2] + breg[j][2];
                zo += xv[ms][j][3] + breg[j][3];
                float ig = fast_sigmoid(zi);
                float fg = fast_sigmoid(zf);
                float og = fast_sigmoid(zo);
                float gg = fast_tanh(zg);
                float c  = fmaf(fg, creg[ms][j], ig * gg);
                creg[ms][j] = c;
                float h  = og * fast_tanh(c);
                __nv_bfloat16 hh = __float2bfloat16(h);
                __nv_bfloat16 hl = __float2bfloat16(h - __bfloat162float(hh));
                unsigned int word = (unsigned int)__bfloat16_as_ushort(hh) |
                                    ((unsigned int)__bfloat16_as_ushort(hl) << 16);
                g_hx[nxt][(b0 + rowb[ms]) * UNITS_ + ht * HN + uloc[j]] = word;
            }
        }

        grid_barrier();   // also orders next step's staging after all MMA reads
    }

    // ---- Final stage: logits = h_final @ Wd + bd ; softmax ----
    // Final h in g_hx[0] (t=511: nxt=0). Each block: 8 batch rows.
    const int rowbase = blockIdx.x * 8;
    float* wd_s   = (float*)smem;               // 128KB (fits in WHI+WLO region)
    float* hrow_s = (float*)(smem + OFF_AHI);   // 8x256 fp32
    float* lg     = (float*)(smem + OFF_ALO);   // 8x128 logits

    for (int idx = tid; idx < UNITS_ * NCHARS; idx += NTHR)
        wd_s[idx] = Wd[idx];
    for (int idx = tid; idx < 8 * UNITS_; idx += NTHR) {
        int r  = idx >> 8;
        int uu = idx & 255;
        unsigned int word = g_hx[0][(rowbase + r) * UNITS_ + uu];
        float h = __bfloat162float(__ushort_as_bfloat16((unsigned short)(word & 0xFFFF))) +
                  __bfloat162float(__ushort_as_bfloat16((unsigned short)(word >> 16)));
        hrow_s[idx] = h;
    }
    __syncthreads();

    {
        int n  = tid & 127;
        int rr = tid >> 7;
#pragma unroll
        for (int q = 0; q < 4; q++) {
            int row = q * 2 + rr;
            float a = bd[n];
#pragma unroll 8
            for (int uu = 0; uu < UNITS_; uu++)
                a = fmaf(hrow_s[row * UNITS_ + uu], wd_s[uu * NCHARS + n], a);
            lg[row * NCHARS + n] = a;
        }
    }
    __syncthreads();

    {   // softmax: one warp per row
        int w = tid >> 5;
        float v[4];
        float mx = -3.402823466e38f;
#pragma unroll
        for (int q = 0; q < 4; q++) {
            v[q] = lg[w * NCHARS + lane + 32 * q];
            mx = fmaxf(mx, v[q]);
        }
#pragma unroll
        for (int s = 16; s > 0; s >>= 1) mx = fmaxf(mx, __shfl_xor_sync(0xFFFFFFFFu, mx, s));
        float sum = 0.f;
#pragma unroll
        for (int q = 0; q < 4; q++) { v[q] = __expf(v[q] - mx); sum += v[q]; }
#pragma unroll
        for (int s = 16; s > 0; s >>= 1) sum += __shfl_xor_sync(0xFFFFFFFFu, sum, s);
        float inv = 1.0f / sum;
        int bg = rowbase + w;
#pragma unroll
        for (int q = 0; q < 4; q++)
            out[bg * NCHARS + lane + 32 * q] = v[q] * inv;
    }
}

extern "C" void kernel_launch(void* const* d_in, const int* in_sizes, int n_in,
                              void* d_out, int out_size) {
    const int*   inputs = (const int*)  d_in[0];
    const float* Wx     = (const float*)d_in[1];
    const float* Wh     = (const float*)d_in[2];
    const float* b      = (const float*)d_in[3];
    const float* Wd     = (const float*)d_in[4];
    const float* bd     = (const float*)d_in[5];
    float* out = (float*)d_out;

    cudaFuncSetAttribute(lstm_hmma_kernel,
                         cudaFuncAttributeMaxDynamicSharedMemorySize, SMEM_TOTAL);

    lstm_hmma_kernel<<<NBLK, NTHR, SMEM_TOTAL>>>(inputs, Wx, Wh, b, Wd, bd, out);
}

// round 11
// speedup vs baseline: 1.2879x; 1.2879x over previous
#include <cuda_runtime.h>
#include <cuda_bf16.h>
#include <cstdint>

// Problem constants
#define NB      1024
#define SEQT    512
#define UNITS_  256
#define NCHARS  128
#define ZC      1024      // 4*UNITS

// Tiling: 128 blocks = 16 batch-tiles x 8 hidden-tiles
// blockIdx = bt*8 + ht  (contiguous 8-block groups share a batch tile)
#define BM      64        // batch rows per block (GEMM M)
#define HN      32        // hidden units per block
#define BC      128       // z cols per block (GEMM N): col = gate*32 + unit
#define NBT     16
#define NHT     8
#define NBLK    128
#define NTHR    256
#define GRPSZ   8         // blocks per barrier group (same bt)

#define KDIM    256       // GEMM K
#define KPB     528       // padded row bytes (264 bf16)
#define ZP      132       // z row stride (floats)

// Shared memory layout (bytes)
#define OFF_WHI   0                         // Whi: [128 n][264 k] bf16 = 67584
#define OFF_WLO   67584                     // Wlo: 67584
#define OFF_AHI   135168                    // Ahi: [64 r][264 k] bf16 = 33792
#define OFF_ALO   168960                    // Alo: 33792
#define OFF_Z     OFF_AHI                   // z: [64][132] fp32 = 33792 (overlay)
#define SMEM_TOTAL 202752

// Device-global scratch (zero-init at load)
__device__ unsigned int g_hx[2][NB * UNITS_];   // packed (bf16 hi | bf16 lo<<16)
struct GSync { unsigned int count; unsigned int gen; unsigned int pad[30]; };
__device__ GSync g_sync[NBT];                   // one 128B line per group

__device__ __forceinline__ float fast_sigmoid(float x) {
    return __fdividef(1.0f, 1.0f + __expf(-x));
}
__device__ __forceinline__ float fast_tanh(float x) {
    float e = __expf(2.0f * x);
    return 1.0f - __fdividef(2.0f, e + 1.0f);
}

// m16n8k16 row.col bf16 -> fp32 accumulate (baseline PTX, legal on sm_103)
__device__ __forceinline__ void mma16816(float& c0, float& c1, float& c2, float& c3,
                                         uint32_t a0, uint32_t a1, uint32_t a2, uint32_t a3,
                                         uint32_t b0, uint32_t b1) {
    asm volatile(
        "mma.sync.aligned.m16n8k16.row.col.f32.bf16.bf16.f32 "
        "{%0,%1,%2,%3}, {%4,%5,%6,%7}, {%8,%9}, {%0,%1,%2,%3};"
        : "+f"(c0), "+f"(c1), "+f"(c2), "+f"(c3)
        : "r"(a0), "r"(a1), "r"(a2), "r"(a3), "r"(b0), "r"(b1));
}

// Sense-reversing barrier over the GRPSZ co-resident CTAs sharing one batch tile.
__device__ __forceinline__ void group_barrier(int grp) {
    __syncthreads();
    if (threadIdx.x == 0) {
        __threadfence();
        unsigned int gen = *(volatile unsigned int*)&g_sync[grp].gen;
        unsigned int c = atomicAdd(&g_sync[grp].count, 1u);
        if (c == GRPSZ - 1u) {
            atomicExch(&g_sync[grp].count, 0u);
            __threadfence();
            atomicAdd(&g_sync[grp].gen, 1u);
        } else {
            while (*(volatile unsigned int*)&g_sync[grp].gen == gen) { __nanosleep(32); }
        }
        __threadfence();
    }
    __syncthreads();
}

extern "C" __global__ void __launch_bounds__(NTHR, 1)
lstm_hmma_kernel(const int*   __restrict__ inputs,   // [NB, SEQT]
                 const float* __restrict__ Wx,       // [NCHARS, ZC]
                 const float* __restrict__ Wh,       // [UNITS, ZC]
                 const float* __restrict__ bias,     // [ZC]
                 const float* __restrict__ Wd,       // [UNITS, NCHARS]
                 const float* __restrict__ bd,       // [NCHARS]
                 float*       __restrict__ out)      // [NB, NCHARS]
{
    extern __shared__ char smem[];
    float* z_s = (float*)(smem + OFF_Z);

    const int tid  = threadIdx.x;
    const int wid  = tid >> 5;
    const int lane = tid & 31;
    const int bt   = blockIdx.x >> 3;   // 0..15 (barrier group)
    const int ht   = blockIdx.x & 7;    // 0..7
    const int b0   = bt * BM;

    // ---- One-time: Wh slice -> bf16 hi/lo, [n][k] with n = gate*32 + unit ----
    for (int idx = tid; idx < BC * KDIM; idx += NTHR) {
        int n = idx >> 8;          // 0..127
        int k = idx & 255;         // 0..255
        int gcol = ((n >> 5) << 8) + ht * HN + (n & 31);
        float w = Wh[k * ZC + gcol];
        __nv_bfloat16 hi = __float2bfloat16(w);
        __nv_bfloat16 lo = __float2bfloat16(w - __bfloat162float(hi));
        *(__nv_bfloat16*)(smem + OFF_WHI + n * KPB + k * 2) = hi;
        *(__nv_bfloat16*)(smem + OFF_WLO + n * KPB + k * 2) = lo;
    }

    // Bias -> registers (coalesced: u = lane)
    const int u = lane;
    float breg[4];
#pragma unroll
    for (int gt = 0; gt < 4; gt++)
        breg[gt] = __ldg(&bias[gt * 256 + ht * HN + u]);

    // zero z region (t=0 gate phase reads zeros)
    for (int idx = tid; idx < BM * ZP; idx += NTHR) z_s[idx] = 0.0f;

    float creg[8];
#pragma unroll
    for (int j = 0; j < 8; j++) creg[j] = 0.0f;

    // MMA warp mapping: warp tile m32 x n32; Wm=2 (wm=wid&1), Wn=4 (wn=wid>>1)
    const int g  = lane >> 2;      // 0..7
    const int tg = lane & 3;       // 0..3
    const int wm = wid & 1;
    const int wn = wid >> 1;
    const int aoffh = OFF_AHI + (32 * wm + g) * KPB + 4 * tg;   // + ms*16*KPB
    const int aoffl = OFF_ALO + (32 * wm + g) * KPB + 4 * tg;
    const int boffh = OFF_WHI + (32 * wn + g) * KPB + 4 * tg;   // + j*8*KPB
    const int boffl = OFF_WLO + (32 * wn + g) * KPB + 4 * tg;

    __syncthreads();

    for (int t = 0; t < SEQT; t++) {
        const int cur = t & 1;
        const int nxt = cur ^ 1;

        // ---- Chars (warp-broadcast) ----
        int ch[8];
#pragma unroll
        for (int j = 0; j < 8; j++)
            ch[j] = __ldg(&inputs[(b0 + wid + 8 * j) * SEQT + t]);

        if (t > 0) {
            // ---- Stage A: split packed h into bf16 hi/lo tiles [64][264] ----
            for (int gidx = tid; gidx < BM * 64; gidx += NTHR) {
                int r  = gidx >> 6;
                int k0 = (gidx & 63) << 2;
                uint4 p = *(const uint4*)&g_hx[cur][(b0 + r) * UNITS_ + k0];
                uint32_t hi01 = __byte_perm(p.x, p.y, 0x5410);
                uint32_t hi23 = __byte_perm(p.z, p.w, 0x5410);
                uint32_t lo01 = __byte_perm(p.x, p.y, 0x7632);
                uint32_t lo23 = __byte_perm(p.z, p.w, 0x7632);
                uint32_t byte = (uint32_t)(r * KPB + k0 * 2);
                *(uint2*)(smem + OFF_AHI + byte) = make_uint2(hi01, hi23);
                *(uint2*)(smem + OFF_ALO + byte) = make_uint2(lo01, lo23);
            }
        }

        // ---- Wx gather (coalesced; overlaps staging/MMA latency) ----
        float xv0[8], xv1[8], xv2[8], xv3[8];
#pragma unroll
        for (int j = 0; j < 8; j++) {
            const float* wxr = Wx + ch[j] * ZC + ht * HN + u;
            xv0[j] = __ldg(wxr);
            xv1[j] = __ldg(wxr + 256);
            xv2[j] = __ldg(wxr + 512);
            xv3[j] = __ldg(wxr + 768);
        }

        if (t > 0) {
            float acc[2][4][4];
#pragma unroll
            for (int ms = 0; ms < 2; ms++)
#pragma unroll
                for (int j = 0; j < 4; j++) {
                    acc[ms][j][0] = 0.f; acc[ms][j][1] = 0.f;
                    acc[ms][j][2] = 0.f; acc[ms][j][3] = 0.f;
                }

            __syncthreads();   // staging complete before fragment reads

            // ---- MMA: C[64][128] = Ahi*Whi + Alo*Whi + Ahi*Wlo ----
#pragma unroll 2
            for (int kc = 0; kc < 16; kc++) {
                const int kb = kc * 32;   // 16 bf16 = 32 bytes
                uint32_t ah[2][4], al[2][4];
#pragma unroll
                for (int ms = 0; ms < 2; ms++) {
                    int ab = aoffh + ms * 16 * KPB + kb;
                    ah[ms][0] = *(const uint32_t*)(smem + ab);
                    ah[ms][1] = *(const uint32_t*)(smem + ab + 8 * KPB);
                    ah[ms][2] = *(const uint32_t*)(smem + ab + 16);
                    ah[ms][3] = *(const uint32_t*)(smem + ab + 8 * KPB + 16);
                    int abl = aoffl + ms * 16 * KPB + kb;
                    al[ms][0] = *(const uint32_t*)(smem + abl);
                    al[ms][1] = *(const uint32_t*)(smem + abl + 8 * KPB);
                    al[ms][2] = *(const uint32_t*)(smem + abl + 16);
                    al[ms][3] = *(const uint32_t*)(smem + abl + 8 * KPB + 16);
                }
#pragma unroll
                for (int j = 0; j < 4; j++) {
                    int bb = boffh + j * 8 * KPB + kb;
                    uint32_t bh0 = *(const uint32_t*)(smem + bb);
                    uint32_t bh1 = *(const uint32_t*)(smem + bb + 16);
                    int bbl = boffl + j * 8 * KPB + kb;
                    uint32_t bl0 = *(const uint32_t*)(smem + bbl);
                    uint32_t bl1 = *(const uint32_t*)(smem + bbl + 16);
#pragma unroll
                    for (int ms = 0; ms < 2; ms++) {
                        mma16816(acc[ms][j][0], acc[ms][j][1], acc[ms][j][2], acc[ms][j][3],
                                 ah[ms][0], ah[ms][1], ah[ms][2], ah[ms][3], bh0, bh1);
                        mma16816(acc[ms][j][0], acc[ms][j][1], acc[ms][j][2], acc[ms][j][3],
                                 al[ms][0], al[ms][1], al[ms][2], al[ms][3], bh0, bh1);
                        mma16816(acc[ms][j][0], acc[ms][j][1], acc[ms][j][2], acc[ms][j][3],
                                 ah[ms][0], ah[ms][1], ah[ms][2], ah[ms][3], bl0, bl1);
                    }
                }
            }
            __syncthreads();   // all A reads done before z overlays A_hi

            // ---- Store z tile (m32n32 accumulator layout -> [row][col]) ----
#pragma unroll
            for (int ms = 0; ms < 2; ms++)
#pragma unroll
                for (int j = 0; j < 4; j++) {
                    int row0 = 32 * wm + 16 * ms + g;
                    int col  = 32 * wn + 8 * j + 2 * tg;
                    *(float2*)(z_s + row0 * ZP + col)       = make_float2(acc[ms][j][0], acc[ms][j][1]);
                    *(float2*)(z_s + (row0 + 8) * ZP + col) = make_float2(acc[ms][j][2], acc[ms][j][3]);
                }
            __syncthreads();
        }

        // ---- Gate phase: coalesced mapping (b = wid + 8j, unit u = lane) ----
#pragma unroll
        for (int j = 0; j < 8; j++) {
            int b = wid + 8 * j;
            float zi = z_s[b * ZP +      u] + xv0[j] + breg[0];
            float zf = z_s[b * ZP + 32 + u] + xv1[j] + breg[1];
            float zg = z_s[b * ZP + 64 + u] + xv2[j] + breg[2];
            float zo = z_s[b * ZP + 96 + u] + xv3[j] + breg[3];
            float ig = fast_sigmoid(zi);
            float fg = fast_sigmoid(zf);
            float og = fast_sigmoid(zo);
            float gg = fast_tanh(zg);
            float c  = fmaf(fg, creg[j], ig * gg);
            creg[j] = c;
            float h  = og * fast_tanh(c);
            __nv_bfloat16 hh = __float2bfloat16(h);
            __nv_bfloat16 hl = __float2bfloat16(h - __bfloat162float(hh));
            unsigned int word = (unsigned int)__bfloat16_as_ushort(hh) |
                                ((unsigned int)__bfloat16_as_ushort(hl) << 16);
            g_hx[nxt][(b0 + b) * UNITS_ + ht * HN + u] = word;
        }

        group_barrier(bt);   // only the 8 blocks sharing this batch tile
    }

    // ---- Final stage: logits = h_final @ Wd + bd ; softmax ----
    // Final h in g_hx[0]. Rows rowbase..rowbase+7 lie inside this block's bt tile,
    // so the last group barrier suffices.
    const int rowbase = blockIdx.x * 8;
    float* wd_s   = (float*)smem;               // 128KB (WHI+WLO region)
    float* hrow_s = (float*)(smem + OFF_ALO);   // 8x256 fp32
    float* lg     = (float*)(smem + OFF_ALO + 8 * 256 * 4); // 8x128 logits

    for (int idx = tid; idx < UNITS_ * NCHARS; idx += NTHR)
        wd_s[idx] = Wd[idx];
    for (int idx = tid; idx < 8 * UNITS_; idx += NTHR) {
        int r  = idx >> 8;
        int uu = idx & 255;
        unsigned int word = g_hx[0][(rowbase + r) * UNITS_ + uu];
        float h = __bfloat162float(__ushort_as_bfloat16((unsigned short)(word & 0xFFFF))) +
                  __bfloat162float(__ushort_as_bfloat16((unsigned short)(word >> 16)));
        hrow_s[idx] = h;
    }
    __syncthreads();

    {
        int n  = tid & 127;
        int rr = tid >> 7;
#pragma unroll
        for (int q = 0; q < 4; q++) {
            int row = q * 2 + rr;
            float a = bd[n];
#pragma unroll 8
            for (int uu = 0; uu < UNITS_; uu++)
                a = fmaf(hrow_s[row * UNITS_ + uu], wd_s[uu * NCHARS + n], a);
            lg[row * NCHARS + n] = a;
        }
    }
    __syncthreads();

    {   // softmax: one warp per row
        int w = tid >> 5;
        float v[4];
        float mx = -3.402823466e38f;
#pragma unroll
        for (int q = 0; q < 4; q++) {
            v[q] = lg[w * NCHARS + lane + 32 * q];
            mx = fmaxf(mx, v[q]);
        }
#pragma unroll
        for (int s = 16; s > 0; s >>= 1) mx = fmaxf(mx, __shfl_xor_sync(0xFFFFFFFFu, mx, s));
        float sum = 0.f;
#pragma unroll
        for (int q = 0; q < 4; q++) { v[q] = __expf(v[q] - mx); sum += v[q]; }
#pragma unroll
        for (int s = 16; s > 0; s >>= 1) sum += __shfl_xor_sync(0xFFFFFFFFu, sum, s);
        float inv = 1.0f / sum;
        int bg = rowbase + w;
#pragma unroll
        for (int q = 0; q < 4; q++)
            out[bg * NCHARS + lane + 32 * q] = v[q] * inv;
    }
}

extern "C" void kernel_launch(void* const* d_in, const int* in_sizes, int n_in,
                              void* d_out, int out_size) {
    const int*   inputs = (const int*)  d_in[0];
    const float* Wx     = (const float*)d_in[1];
    const float* Wh     = (const float*)d_in[2];
    const float* b      = (const float*)d_in[3];
    const float* Wd     = (const float*)d_in[4];
    const float* bd     = (const float*)d_in[5];
    float* out = (float*)d_out;

    cudaFuncSetAttribute(lstm_hmma_kernel,
                         cudaFuncAttributeMaxDynamicSharedMemorySize, SMEM_TOTAL);

    lstm_hmma_kernel<<<NBLK, NTHR, SMEM_TOTAL>>>(inputs, Wx, Wh, b, Wd, bd, out);
}

// round 12
// speedup vs baseline: 1.3561x; 1.0529x over previous
#include <cuda_runtime.h>
#include <cuda_bf16.h>
#include <cstdint>

// Problem constants
#define NB      1024
#define SEQT    512
#define UNITS_  256
#define NCHARS  128
#define ZC      1024      // 4*UNITS

// Tiling: 128 blocks = 16 batch-tiles x 8 hidden-tiles
// blockIdx = bt*8 + ht  (contiguous 8-block groups share a batch tile)
#define BM      64        // batch rows per block (GEMM M)
#define HN      32        // hidden units per block
#define BC      128       // z cols per block (GEMM N): col = gate*32 + unit
#define NBT     16
#define NHT     8
#define NBLK    128
#define NTHR    256
#define GRPSZ   8         // blocks per barrier group (same bt)

#define KDIM    256       // GEMM K
#define KPB     528       // padded row bytes (264 bf16)
#define ZP      132       // z row stride (floats)

// Shared memory layout (bytes)
#define OFF_WHI   0                         // Whi: [128 n][264 k] bf16 = 67584
#define OFF_WLO   67584                     // Wlo: 67584
#define OFF_AHI   135168                    // Ahi: [64 r][264 k] bf16 = 33792
#define OFF_ALO   168960                    // Alo: 33792
#define OFF_Z     OFF_AHI                   // z: [64][132] fp32 = 33792 (overlay)
#define SMEM_TOTAL 202752

// Device-global scratch (zero-init at load)
__device__ unsigned int g_hx[2][NB * UNITS_];   // packed (bf16 hi | bf16 lo<<16)
struct GSync { unsigned int count; unsigned int gen; unsigned int pad[30]; };
__device__ GSync g_sync[NBT];                   // one 128B line per group

__device__ __forceinline__ uint32_t smem_u32(const void* p) {
    uint32_t a;
    asm("{ .reg .u64 t; cvta.to.shared.u64 t, %1; cvt.u32.u64 %0, t; }" : "=r"(a) : "l"(p));
    return a;
}

__device__ __forceinline__ float fast_sigmoid(float x) {
    return __fdividef(1.0f, 1.0f + __expf(-x));
}
__device__ __forceinline__ float fast_tanh(float x) {
    float e = __expf(2.0f * x);
    return 1.0f - __fdividef(2.0f, e + 1.0f);
}

// m16n8k16 row.col bf16 -> fp32 accumulate (baseline PTX)
__device__ __forceinline__ void mma16816(float& c0, float& c1, float& c2, float& c3,
                                         uint32_t a0, uint32_t a1, uint32_t a2, uint32_t a3,
                                         uint32_t b0, uint32_t b1) {
    asm volatile(
        "mma.sync.aligned.m16n8k16.row.col.f32.bf16.bf16.f32 "
        "{%0,%1,%2,%3}, {%4,%5,%6,%7}, {%8,%9}, {%0,%1,%2,%3};"
        : "+f"(c0), "+f"(c1), "+f"(c2), "+f"(c3)
        : "r"(a0), "r"(a1), "r"(a2), "r"(a3), "r"(b0), "r"(b1));
}

// ldmatrix x4 (baseline PTX sm_75+): 4 m8n8 b16 matrices, one row addr per lane
#define LDSM4(r, addr) \
    asm volatile("ldmatrix.sync.aligned.m8n8.x4.shared.b16 {%0,%1,%2,%3}, [%4];" \
        : "=r"((r)[0]), "=r"((r)[1]), "=r"((r)[2]), "=r"((r)[3]) : "r"(addr))

// Sense-reversing barrier over the GRPSZ co-resident CTAs sharing one batch tile.
__device__ __forceinline__ void group_barrier(int grp) {
    __syncthreads();
    if (threadIdx.x == 0) {
        __threadfence();
        unsigned int gen = *(volatile unsigned int*)&g_sync[grp].gen;
        unsigned int c = atomicAdd(&g_sync[grp].count, 1u);
        if (c == GRPSZ - 1u) {
            atomicExch(&g_sync[grp].count, 0u);
            __threadfence();
            atomicAdd(&g_sync[grp].gen, 1u);
        } else {
            while (*(volatile unsigned int*)&g_sync[grp].gen == gen) { __nanosleep(32); }
        }
        __threadfence();
    }
    __syncthreads();
}

// One K-half (8 k-chunks) of the 3-pass MMA. kbase = 0 or 256 bytes.
__device__ __forceinline__ void mma_half(float acc[2][4][4],
                                         uint32_t ahi0, uint32_t alo0,
                                         uint32_t bhi0, uint32_t blo0, int kbase)
{
#pragma unroll 2
    for (int kc = 0; kc < 8; kc++) {
        const int kb = kbase + kc * 32;   // 16 bf16 = 32 bytes
        uint32_t ah0[4], ah1[4], al0[4], al1[4];
        uint32_t bh0[4], bh1[4], bl0[4], bl1[4];
        LDSM4(ah0, ahi0 + kb);
        LDSM4(ah1, ahi0 + 16 * KPB + kb);
        LDSM4(al0, alo0 + kb);
        LDSM4(al1, alo0 + 16 * KPB + kb);
        LDSM4(bh0, bhi0 + kb);
        LDSM4(bh1, bhi0 + 16 * KPB + kb);
        LDSM4(bl0, blo0 + kb);
        LDSM4(bl1, blo0 + 16 * KPB + kb);
        uint32_t* ahp[2] = {ah0, ah1};
        uint32_t* alp[2] = {al0, al1};
        uint32_t* bhj[4] = {bh0, bh0 + 2, bh1, bh1 + 2};
        uint32_t* blj[4] = {bl0, bl0 + 2, bl1, bl1 + 2};
#pragma unroll
        for (int j = 0; j < 4; j++) {
#pragma unroll
            for (int ms = 0; ms < 2; ms++) {
                mma16816(acc[ms][j][0], acc[ms][j][1], acc[ms][j][2], acc[ms][j][3],
                         ahp[ms][0], ahp[ms][1], ahp[ms][2], ahp[ms][3],
                         bhj[j][0], bhj[j][1]);
                mma16816(acc[ms][j][0], acc[ms][j][1], acc[ms][j][2], acc[ms][j][3],
                         alp[ms][0], alp[ms][1], alp[ms][2], alp[ms][3],
                         bhj[j][0], bhj[j][1]);
                mma16816(acc[ms][j][0], acc[ms][j][1], acc[ms][j][2], acc[ms][j][3],
                         ahp[ms][0], ahp[ms][1], ahp[ms][2], ahp[ms][3],
                         blj[j][0], blj[j][1]);
            }
        }
    }
}

extern "C" __global__ void __launch_bounds__(NTHR, 1)
lstm_hmma_kernel(const int*   __restrict__ inputs,   // [NB, SEQT]
                 const float* __restrict__ Wx,       // [NCHARS, ZC]
                 const float* __restrict__ Wh,       // [UNITS, ZC]
                 const float* __restrict__ bias,     // [ZC]
                 const float* __restrict__ Wd,       // [UNITS, NCHARS]
                 const float* __restrict__ bd,       // [NCHARS]
                 float*       __restrict__ out)      // [NB, NCHARS]
{
    extern __shared__ char smem[];
    float* z_s = (float*)(smem + OFF_Z);
    const uint32_t sb = smem_u32(smem);

    const int tid  = threadIdx.x;
    const int wid  = tid >> 5;
    const int lane = tid & 31;
    const int bt   = blockIdx.x >> 3;   // 0..15 (barrier group)
    const int ht   = blockIdx.x & 7;    // 0..7
    const int b0   = bt * BM;

    // ---- One-time: Wh slice -> bf16 hi/lo, [n][k] with n = gate*32 + unit ----
    for (int idx = tid; idx < BC * KDIM; idx += NTHR) {
        int n = idx >> 8;          // 0..127
        int k = idx & 255;         // 0..255
        int gcol = ((n >> 5) << 8) + ht * HN + (n & 31);
        float w = Wh[k * ZC + gcol];
        __nv_bfloat16 hi = __float2bfloat16(w);
        __nv_bfloat16 lo = __float2bfloat16(w - __bfloat162float(hi));
        *(__nv_bfloat16*)(smem + OFF_WHI + n * KPB + k * 2) = hi;
        *(__nv_bfloat16*)(smem + OFF_WLO + n * KPB + k * 2) = lo;
    }

    // Bias -> registers (coalesced: u = lane)
    const int u = lane;
    float breg[4];
#pragma unroll
    for (int gt = 0; gt < 4; gt++)
        breg[gt] = __ldg(&bias[gt * 256 + ht * HN + u]);

    // zero z region (t=0 gate phase reads zeros)
    for (int idx = tid; idx < BM * ZP; idx += NTHR) z_s[idx] = 0.0f;

    float creg[8];
#pragma unroll
    for (int j = 0; j < 8; j++) creg[j] = 0.0f;

    // MMA warp mapping: warp tile m32 x n32; Wm=2 (wm=wid&1), Wn=4 (wn=wid>>1)
    const int g  = lane >> 2;      // 0..7
    const int tg = lane & 3;       // 0..3
    const int wm = wid & 1;
    const int wn = wid >> 1;

    // ldmatrix per-lane row addresses (x4 matrix order matches mma frag order)
    const int l7 = lane & 7;
    const int qq = lane >> 3;      // quad 0..3
    // A x4 mats: (m0-7,kb),(m8-15,kb),(m0-7,kb+16),(m8-15,kb+16)
    const uint32_t ahi0 = sb + OFF_AHI + (uint32_t)((32 * wm + l7 + 8 * (qq & 1)) * KPB + 16 * (qq >> 1));
    const uint32_t alo0 = sb + OFF_ALO + (uint32_t)((32 * wm + l7 + 8 * (qq & 1)) * KPB + 16 * (qq >> 1));
    // B x4 mats: (n0-7,kb),(n0-7,kb+16),(n8-15,kb),(n8-15,kb+16)  [pair j,j+1]
    const uint32_t bhi0 = sb + OFF_WHI + (uint32_t)((32 * wn + 8 * (qq >> 1) + l7) * KPB + 16 * (qq & 1));
    const uint32_t blo0 = sb + OFF_WLO + (uint32_t)((32 * wn + 8 * (qq >> 1) + l7) * KPB + 16 * (qq & 1));

    __syncthreads();

    for (int t = 0; t < SEQT; t++) {
        const int cur = t & 1;
        const int nxt = cur ^ 1;

        // ---- Chars (warp-broadcast) ----
        int ch[8];
#pragma unroll
        for (int j = 0; j < 8; j++)
            ch[j] = __ldg(&inputs[(b0 + wid + 8 * j) * SEQT + t]);

        uint4 pp[8];   // upper-half h words, in flight across lower-half MMA
        if (t > 0) {
            // ---- Stage A lower K half: k in [0,128) ----
#pragma unroll
            for (int i = 0; i < 8; i++) {
                int gidx = tid + i * NTHR;      // over BM*32 groups
                int r  = gidx >> 5;
                int kq = gidx & 31;             // k0 = 4*kq
                uint4 p = *(const uint4*)&g_hx[cur][(b0 + r) * UNITS_ + 4 * kq];
                uint32_t hi01 = __byte_perm(p.x, p.y, 0x5410);
                uint32_t hi23 = __byte_perm(p.z, p.w, 0x5410);
                uint32_t lo01 = __byte_perm(p.x, p.y, 0x7632);
                uint32_t lo23 = __byte_perm(p.z, p.w, 0x7632);
                uint32_t byte = (uint32_t)(r * KPB + 8 * kq);
                *(uint2*)(smem + OFF_AHI + byte) = make_uint2(hi01, hi23);
                *(uint2*)(smem + OFF_ALO + byte) = make_uint2(lo01, lo23);
            }
            // ---- Issue upper-half LDGs (latency hidden under lower-half MMA) ----
#pragma unroll
            for (int i = 0; i < 8; i++) {
                int gidx = tid + i * NTHR;
                int r  = gidx >> 5;
                int kq = 32 + (gidx & 31);
                pp[i] = *(const uint4*)&g_hx[cur][(b0 + r) * UNITS_ + 4 * kq];
            }
        }

        // ---- Wx gather (coalesced; overlaps staging/MMA latency) ----
        float xv0[8], xv1[8], xv2[8], xv3[8];
#pragma unroll
        for (int j = 0; j < 8; j++) {
            const float* wxr = Wx + ch[j] * ZC + ht * HN + u;
            xv0[j] = __ldg(wxr);
            xv1[j] = __ldg(wxr + 256);
            xv2[j] = __ldg(wxr + 512);
            xv3[j] = __ldg(wxr + 768);
        }

        if (t > 0) {
            float acc[2][4][4];
#pragma unroll
            for (int ms = 0; ms < 2; ms++)
#pragma unroll
                for (int j = 0; j < 4; j++) {
                    acc[ms][j][0] = 0.f; acc[ms][j][1] = 0.f;
                    acc[ms][j][2] = 0.f; acc[ms][j][3] = 0.f;
                }

            __syncthreads();   // lower-half staging visible

            // ---- MMA on lower K half (upper-half LDGs still in flight) ----
            mma_half(acc, ahi0, alo0, bhi0, blo0, 0);

            // ---- Store upper half (disjoint bytes from lower-half reads) ----
#pragma unroll
            for (int i = 0; i < 8; i++) {
                int gidx = tid + i * NTHR;
                int r  = gidx >> 5;
                int kq = 32 + (gidx & 31);
                uint4 p = pp[i];
                uint32_t hi01 = __byte_perm(p.x, p.y, 0x5410);
                uint32_t hi23 = __byte_perm(p.z, p.w, 0x5410);
                uint32_t lo01 = __byte_perm(p.x, p.y, 0x7632);
                uint32_t lo23 = __byte_perm(p.z, p.w, 0x7632);
                uint32_t byte = (uint32_t)(r * KPB + 8 * kq);
                *(uint2*)(smem + OFF_AHI + byte) = make_uint2(hi01, hi23);
                *(uint2*)(smem + OFF_ALO + byte) = make_uint2(lo01, lo23);
            }
            __syncthreads();   // upper-half staging visible

            // ---- MMA on upper K half ----
            mma_half(acc, ahi0, alo0, bhi0, blo0, 256);

            __syncthreads();   // all A reads done before z overlays A_hi

            // ---- Store z tile (m32n32 accumulator layout -> [row][col]) ----
#pragma unroll
            for (int ms = 0; ms < 2; ms++)
#pragma unroll
                for (int j = 0; j < 4; j++) {
                    int row0 = 32 * wm + 16 * ms + g;
                    int col  = 32 * wn + 8 * j + 2 * tg;
                    *(float2*)(z_s + row0 * ZP + col)       = make_float2(acc[ms][j][0], acc[ms][j][1]);
                    *(float2*)(z_s + (row0 + 8) * ZP + col) = make_float2(acc[ms][j][2], acc[ms][j][3]);
                }
            __syncthreads();
        }

        // ---- Gate phase: coalesced mapping (b = wid + 8j, unit u = lane) ----
#pragma unroll
        for (int j = 0; j < 8; j++) {
            int b = wid + 8 * j;
            float zi = z_s[b * ZP +      u] + xv0[j] + breg[0];
            float zf = z_s[b * ZP + 32 + u] + xv1[j] + breg[1];
            float zg = z_s[b * ZP + 64 + u] + xv2[j] + breg[2];
            float zo = z_s[b * ZP + 96 + u] + xv3[j] + breg[3];
            float ig = fast_sigmoid(zi);
            float fg = fast_sigmoid(zf);
            float og = fast_sigmoid(zo);
            float gg = fast_tanh(zg);
            float c  = fmaf(fg, creg[j], ig * gg);
            creg[j] = c;
            float h  = og * fast_tanh(c);
            __nv_bfloat16 hh = __float2bfloat16(h);
            __nv_bfloat16 hl = __float2bfloat16(h - __bfloat162float(hh));
            unsigned int word = (unsigned int)__bfloat16_as_ushort(hh) |
                                ((unsigned int)__bfloat16_as_ushort(hl) << 16);
            g_hx[nxt][(b0 + b) * UNITS_ + ht * HN + u] = word;
        }

        group_barrier(bt);   // only the 8 blocks sharing this batch tile
    }

    // ---- Final stage: logits = h_final @ Wd + bd ; softmax ----
    const int rowbase = blockIdx.x * 8;
    float* wd_s   = (float*)smem;               // 128KB (WHI+WLO region)
    float* hrow_s = (float*)(smem + OFF_ALO);   // 8x256 fp32
    float* lg     = (float*)(smem + OFF_ALO + 8 * 256 * 4); // 8x128 logits

    for (int idx = tid; idx < UNITS_ * NCHARS; idx += NTHR)
        wd_s[idx] = Wd[idx];
    for (int idx = tid; idx < 8 * UNITS_; idx += NTHR) {
        int r  = idx >> 8;
        int uu = idx & 255;
        unsigned int word = g_hx[0][(rowbase + r) * UNITS_ + uu];
        float h = __bfloat162float(__ushort_as_bfloat16((unsigned short)(word & 0xFFFF))) +
                  __bfloat162float(__ushort_as_bfloat16((unsigned short)(word >> 16)));
        hrow_s[idx] = h;
    }
    __syncthreads();

    {
        int n  = tid & 127;
        int rr = tid >> 7;
#pragma unroll
        for (int q = 0; q < 4; q++) {
            int row = q * 2 + rr;
            float a = bd[n];
#pragma unroll 8
            for (int uu = 0; uu < UNITS_; uu++)
                a = fmaf(hrow_s[row * UNITS_ + uu], wd_s[uu * NCHARS + n], a);
            lg[row * NCHARS + n] = a;
        }
    }
    __syncthreads();

    {   // softmax: one warp per row
        int w = tid >> 5;
        float v[4];
        float mx = -3.402823466e38f;
#pragma unroll
        for (int q = 0; q < 4; q++) {
            v[q] = lg[w * NCHARS + lane + 32 * q];
            mx = fmaxf(mx, v[q]);
        }
#pragma unroll
        for (int s = 16; s > 0; s >>= 1) mx = fmaxf(mx, __shfl_xor_sync(0xFFFFFFFFu, mx, s));
        float sum = 0.f;
#pragma unroll
        for (int q = 0; q < 4; q++) { v[q] = __expf(v[q] - mx); sum += v[q]; }
#pragma unroll
        for (int s = 16; s > 0; s >>= 1) sum += __shfl_xor_sync(0xFFFFFFFFu, sum, s);
        float inv = 1.0f / sum;
        int bg = rowbase + w;
#pragma unroll
        for (int q = 0; q < 4; q++)
            out[bg * NCHARS + lane + 32 * q] = v[q] * inv;
    }
}

extern "C" void kernel_launch(void* const* d_in, const int* in_sizes, int n_in,
                              void* d_out, int out_size) {
    const int*   inputs = (const int*)  d_in[0];
    const float* Wx     = (const float*)d_in[1];
    const float* Wh     = (const float*)d_in[2];
    const float* b      = (const float*)d_in[3];
    const float* Wd     = (const float*)d_in[4];
    const float* bd     = (const float*)d_in[5];
    float* out = (float*)d_out;

    cudaFuncSetAttribute(lstm_hmma_kernel,
                         cudaFuncAttributeMaxDynamicSharedMemorySize, SMEM_TOTAL);

    lstm_hmma_kernel<<<NBLK, NTHR, SMEM_TOTAL>>>(inputs, Wx, Wh, b, Wd, bd, out);
}